// round 7
// baseline (speedup 1.0000x reference)
#include <cuda_runtime.h>
#include <cuda_fp16.h>
#include <cstdint>

#define Bn   4
#define CIN  64
#define Hc   128
#define Wc   128
#define COUT 64
#define DGn  8
#define KKn  9
#define HOn  128
#define WOn  128
#define CGn  8
#define HWp  (HOn * WOn)

// ---------------- scratch (device globals; no runtime alloc) ----------------
__device__ __half g_xh[Bn * DGn * Hc * Wc * CGn];   // x: [b][dg][y][x][cg] fp16
__device__ __half g_wh[KKn * COUT * CIN];           // weight: per-tap [o][c] fp16, PRE-SWIZZLED SW128

#define SWZ(off) ((off) ^ (((off) >> 3) & 0x70))

// ---------------- smem layout (dynamic, 106496 B) ----------------
#define SM_A0    0
#define SM_A1    16384
#define SM_W     32768
#define SM_TOTAL (32768 + KKn * 8192)

static __device__ __forceinline__ uint32_t smem_u32(const void* p) {
    uint32_t a;
    asm("{ .reg .u64 t; cvta.to.shared.u64 t, %1; cvt.u32.u64 %0, t; }" : "=r"(a) : "l"(p));
    return a;
}
static __device__ __forceinline__ void ldsm_x4(uint32_t* r, uint32_t addr) {
    asm volatile("ldmatrix.sync.aligned.m8n8.x4.shared.b16 {%0,%1,%2,%3}, [%4];"
                 : "=r"(r[0]), "=r"(r[1]), "=r"(r[2]), "=r"(r[3]) : "r"(addr));
}
static __device__ __forceinline__ void mma_f16(float* d, const uint32_t* a, const uint32_t* b) {
    asm volatile("mma.sync.aligned.m16n8k16.row.col.f32.f16.f16.f32 "
                 "{%0,%1,%2,%3}, {%4,%5,%6,%7}, {%8,%9}, {%0,%1,%2,%3};"
                 : "+f"(d[0]), "+f"(d[1]), "+f"(d[2]), "+f"(d[3])
                 : "r"(a[0]), "r"(a[1]), "r"(a[2]), "r"(a[3]), "r"(b[0]), "r"(b[1]));
}

// ---------------------------------------------------------------------------
// Merged prep: blocks [0, 1024) transpose x (512 px x 8ch each, fp16 out);
// blocks [1024, 1024+9) build the per-tap swizzled fp16 weight tiles.
// ---------------------------------------------------------------------------
__global__ void prep_kernel(const float* __restrict__ x, const float* __restrict__ w) {
    const int tid = threadIdx.x;
    if (blockIdx.x < 1024) {
        __shared__ float s[8][516];                 // stride%32==4 -> conflict-free both phases
        const int blk = blockIdx.x;
        const int b   = blk >> 8;                   // 256 blocks per batch
        const int dg  = (blk >> 5) & 7;             // 32 blocks per dg
        const int p0  = (blk & 31) * 512;
        #pragma unroll
        for (int ch = 0; ch < 8; ++ch) {
            const float* src = x + (size_t)(b * CIN + dg * CGn + ch) * (Hc * Wc) + p0;
            s[ch][tid]       = src[tid];
            s[ch][tid + 256] = src[tid + 256];
        }
        __syncthreads();
        __half2* dst = (__half2*)(g_xh + ((size_t)(b * DGn + dg) * (Hc * Wc) + p0) * CGn);
        #pragma unroll
        for (int i = 0; i < 8; ++i) {
            const int j = i * 512 + tid * 2;
            dst[i * 256 + tid] = __floats2half2_rn(s[j & 7][j >> 3], s[(j + 1) & 7][(j + 1) >> 3]);
        }
    } else {
        const int kk = blockIdx.x - 1024;
        #pragma unroll
        for (int r = 0; r < 16; ++r) {
            const int idx = r * 256 + tid;          // idx = o*64 + c
            const int o = idx >> 6;
            const int c = idx & 63;
            const float v = w[(size_t)(o * CIN + c) * KKn + kk];
            const uint32_t off = SWZ((uint32_t)(o * 128 + c * 2));
            g_wh[(size_t)kk * 4096 + off / 2] = __float2half_rn(v);
        }
    }
}

// ---------------------------------------------------------------------------
// Fused deformable conv, software-pipelined. Block = one output row (b,y).
// Double-buffered A tile: iteration kk samples tap kk+1 while MMAing tap kk;
// one __syncthreads per tap. fp32 accumulators across all 9 taps.
// ---------------------------------------------------------------------------
__global__ void __launch_bounds__(256, 2) dcn_kernel(
    const float* __restrict__ offset,
    const float* __restrict__ bias,
    float* __restrict__ out)
{
    extern __shared__ char smem[];
    const uint32_t smb = smem_u32(smem);
    const int bid = blockIdx.x;
    const int b   = bid >> 7;
    const int y   = bid & 127;
    const int tid = threadIdx.x;
    const int wid = tid >> 5;
    const int lid = tid & 31;
    const int m0  = wid * 16;

    float d[8][4];
    #pragma unroll
    for (int i = 0; i < 8; ++i)
        #pragma unroll
        for (int j = 0; j < 4; ++j)
            d[i][j] = 0.0f;

    // stage ALL 9 weight tiles once (72KB, pre-swizzled); first use after prologue sync
    {
        const uint4* src = (const uint4*)g_wh;
        uint4* dst = (uint4*)(smem + SM_W);
        #pragma unroll
        for (int i = 0; i < 18; ++i)
            dst[i * 256 + tid] = src[i * 256 + tid];
    }

    const float* off_b = offset + (size_t)b * (2 * DGn * KKn * HWp) + (size_t)y * WOn;
    const __half* xh_b = g_xh + (size_t)b * (DGn * Hc * Wc * CGn);

    // ---- sampling for one tap into the given A buffer ----
    auto sample_tap = [&](int kk, uint32_t abase) {
        const int kh = kk / 3;
        const int kw = kk - kh * 3;
        #pragma unroll
        for (int it = 0; it < 4; ++it) {
            const int t  = tid + it * 256;
            const int dg = t >> 7;
            const int px = t & 127;

            const float* op = off_b + (size_t)((dg * KKn + kk) * 2) * HWp + px;
            const float oy = op[0];
            const float ox = op[HWp];

            const float py  = (float)(y - 1 + kh) + oy;
            const float pxx = (float)(px - 1 + kw) + ox;
            const float y0f = floorf(py);
            const float x0f = floorf(pxx);
            const float ly  = py - y0f;
            const float lx  = pxx - x0f;
            const int y0 = (int)y0f;
            const int x0 = (int)x0f;
            const float hy = 1.0f - ly, hx = 1.0f - lx;

            float w00 = hy * hx, w01 = hy * lx, w10 = ly * hx, w11 = ly * lx;
            const bool yv0 = (y0 >= 0) && (y0 < Hc);
            const bool yv1 = (y0 + 1 >= 0) && (y0 + 1 < Hc);
            const bool xv0 = (x0 >= 0) && (x0 < Wc);
            const bool xv1 = (x0 + 1 >= 0) && (x0 + 1 < Wc);
            if (!(yv0 && xv0)) w00 = 0.0f;
            if (!(yv0 && xv1)) w01 = 0.0f;
            if (!(yv1 && xv0)) w10 = 0.0f;
            if (!(yv1 && xv1)) w11 = 0.0f;

            const int iy0 = min(max(y0, 0), Hc - 1);
            const int iy1 = min(max(y0 + 1, 0), Hc - 1);
            const int ix0 = min(max(x0, 0), Wc - 1);
            const int ix1 = min(max(x0 + 1, 0), Wc - 1);

            const __half* xg = xh_b + (size_t)dg * (Hc * Wc * CGn);
            const uint4 q00 = *(const uint4*)(xg + (size_t)(iy0 * Wc + ix0) * CGn);
            const uint4 q01 = *(const uint4*)(xg + (size_t)(iy0 * Wc + ix1) * CGn);
            const uint4 q10 = *(const uint4*)(xg + (size_t)(iy1 * Wc + ix0) * CGn);
            const uint4 q11 = *(const uint4*)(xg + (size_t)(iy1 * Wc + ix1) * CGn);
            const __half2* c00 = (const __half2*)&q00;
            const __half2* c01 = (const __half2*)&q01;
            const __half2* c10 = (const __half2*)&q10;
            const __half2* c11 = (const __half2*)&q11;

            const __half2 wv00 = __float2half2_rn(w00);
            const __half2 wv01 = __float2half2_rn(w01);
            const __half2 wv10 = __float2half2_rn(w10);
            const __half2 wv11 = __float2half2_rn(w11);

            __half2 v2[4];
            #pragma unroll
            for (int j = 0; j < 4; ++j) {
                __half2 acc = __hmul2(c00[j], wv00);
                acc = __hfma2(c01[j], wv01, acc);
                acc = __hfma2(c10[j], wv10, acc);
                acc = __hfma2(c11[j], wv11, acc);
                v2[j] = acc;
            }
            const uint32_t aoff = SWZ((uint32_t)(px * 128 + dg * 16));
            *(uint4*)(smem + abase + aoff) = *(const uint4*)v2;
        }
    };

    // prologue: fill buffer 0 with tap 0
    sample_tap(0, SM_A0);
    __syncthreads();

    for (int kk = 0; kk < KKn; ++kk) {
        const uint32_t cur = (kk & 1) ? SM_A1 : SM_A0;
        const uint32_t nxt = (kk & 1) ? SM_A0 : SM_A1;

        // sample next tap first (long-latency LDGs retire under the MMAs below)
        if (kk + 1 < KKn) sample_tap(kk + 1, nxt);

        // ---- MMA tap kk from `cur` ----
        uint32_t ah[4][4];
        {
            const uint32_t arow = (uint32_t)(m0 + (lid & 15));
            const uint32_t akg  = (uint32_t)(lid >> 4);
            #pragma unroll
            for (int ks = 0; ks < 4; ++ks) {
                const uint32_t off = SWZ(arow * 128 + (uint32_t)(ks * 32) + akg * 16);
                ldsm_x4(ah[ks], smb + cur + off);
            }
        }
        {
            const uint32_t wbase = smb + SM_W + (uint32_t)kk * 8192;
            const uint32_t bm  = (uint32_t)(lid >> 3);
            const uint32_t bj  = (uint32_t)(lid & 7);
            #pragma unroll
            for (int np = 0; np < 4; ++np) {
                const uint32_t brow = (uint32_t)(np * 16) + (bm >> 1) * 8 + bj;
                #pragma unroll
                for (int ks = 0; ks < 4; ++ks) {
                    const uint32_t off = SWZ(brow * 128 + (uint32_t)(ks * 32) + (bm & 1) * 16);
                    uint32_t bh[4];
                    ldsm_x4(bh, wbase + off);
                    mma_f16(d[2 * np],     ah[ks], &bh[0]);
                    mma_f16(d[2 * np + 1], ah[ks], &bh[2]);
                }
            }
        }
        __syncthreads();   // next-buffer writes complete + cur free for reuse
    }

    // ---- epilogue: fragments -> global, +bias ----
    {
        const int px0 = m0 + (lid >> 2);
        float* ob = out + (size_t)b * (COUT * HWp) + (size_t)y * WOn;
        #pragma unroll
        for (int nt = 0; nt < 8; ++nt) {
            const int o0 = nt * 8 + 2 * (lid & 3);
            const float2 bv = *(const float2*)&bias[o0];
            ob[(size_t)o0 * HWp + px0]           = d[nt][0] + bv.x;
            ob[(size_t)(o0 + 1) * HWp + px0]     = d[nt][1] + bv.y;
            ob[(size_t)o0 * HWp + px0 + 8]       = d[nt][2] + bv.x;
            ob[(size_t)(o0 + 1) * HWp + px0 + 8] = d[nt][3] + bv.y;
        }
    }
}

extern "C" void kernel_launch(void* const* d_in, const int* in_sizes, int n_in,
                              void* d_out, int out_size) {
    const float* x      = (const float*)d_in[0];
    const float* offset = (const float*)d_in[1];
    const float* weight = (const float*)d_in[2];
    const float* bias   = (const float*)d_in[3];
    float* out = (float*)d_out;

    cudaFuncSetAttribute(dcn_kernel, cudaFuncAttributeMaxDynamicSharedMemorySize, SM_TOTAL);

    prep_kernel<<<1024 + KKn, 256>>>(x, weight);
    dcn_kernel<<<Bn * HOn, 256, SM_TOTAL>>>(offset, bias, out);
}

// round 8
// speedup vs baseline: 1.0603x; 1.0603x over previous
#include <cuda_runtime.h>
#include <cuda_fp16.h>
#include <cstdint>

#define Bn   4
#define CIN  64
#define Hc   128
#define Wc   128
#define COUT 64
#define DGn  8
#define KKn  9
#define HOn  128
#define WOn  128
#define CGn  8
#define HWp  (HOn * WOn)

// ---------------- scratch (device globals; no runtime alloc) ----------------
__device__ __half g_xh[Bn * DGn * Hc * Wc * CGn];   // x: [b][dg][y][x][cg] fp16
// Weights pre-permuted into per-lane HMMA B-fragment order:
// g_wb[((kk*8 + nt)*2 + ksp)*32 + lane] = 16B = {b0,b1}(ks=2ksp), {b0,b1}(ks=2ksp+1)
__device__ uint4 g_wb[KKn * 8 * 2 * 32];

#define SWZ(off) ((off) ^ (((off) >> 3) & 0x70))

// ---------------- smem layout (dynamic, 32768 B) ----------------
#define SM_A0    0
#define SM_A1    16384
#define SM_TOTAL 32768

static __device__ __forceinline__ uint32_t smem_u32(const void* p) {
    uint32_t a;
    asm("{ .reg .u64 t; cvta.to.shared.u64 t, %1; cvt.u32.u64 %0, t; }" : "=r"(a) : "l"(p));
    return a;
}
static __device__ __forceinline__ void ldsm_x4(uint32_t* r, uint32_t addr) {
    asm volatile("ldmatrix.sync.aligned.m8n8.x4.shared.b16 {%0,%1,%2,%3}, [%4];"
                 : "=r"(r[0]), "=r"(r[1]), "=r"(r[2]), "=r"(r[3]) : "r"(addr));
}
static __device__ __forceinline__ void mma_f16(float* d, const uint32_t* a, uint32_t b0, uint32_t b1) {
    asm volatile("mma.sync.aligned.m16n8k16.row.col.f32.f16.f16.f32 "
                 "{%0,%1,%2,%3}, {%4,%5,%6,%7}, {%8,%9}, {%0,%1,%2,%3};"
                 : "+f"(d[0]), "+f"(d[1]), "+f"(d[2]), "+f"(d[3])
                 : "r"(a[0]), "r"(a[1]), "r"(a[2]), "r"(a[3]), "r"(b0), "r"(b1));
}

// ---------------------------------------------------------------------------
// Merged prep: blocks [0,1024) transpose x (512 px x 8ch, fp16 out);
// blocks [1024,1033) build per-tap B fragments in per-lane order.
// ---------------------------------------------------------------------------
__global__ void prep_kernel(const float* __restrict__ x, const float* __restrict__ w) {
    const int tid = threadIdx.x;
    if (blockIdx.x < 1024) {
        __shared__ float s[8][516];
        const int blk = blockIdx.x;
        const int b   = blk >> 8;
        const int dg  = (blk >> 5) & 7;
        const int p0  = (blk & 31) * 512;
        #pragma unroll
        for (int ch = 0; ch < 8; ++ch) {
            const float* src = x + (size_t)(b * CIN + dg * CGn + ch) * (Hc * Wc) + p0;
            s[ch][tid]       = src[tid];
            s[ch][tid + 256] = src[tid + 256];
        }
        __syncthreads();
        __half2* dst = (__half2*)(g_xh + ((size_t)(b * DGn + dg) * (Hc * Wc) + p0) * CGn);
        #pragma unroll
        for (int i = 0; i < 8; ++i) {
            const int j = i * 512 + tid * 2;
            dst[i * 256 + tid] = __floats2half2_rn(s[j & 7][j >> 3], s[(j + 1) & 7][(j + 1) >> 3]);
        }
    } else {
        const int kk = blockIdx.x - 1024;
        #pragma unroll
        for (int r = 0; r < 2; ++r) {
            const int idx  = r * 256 + tid;      // 0..511 entries
            const int nt   = idx >> 6;           // 0..7
            const int ksp  = (idx >> 5) & 1;     // 0..1
            const int lane = idx & 31;
            const int n    = nt * 8 + (lane >> 2);
            __half h[8];
            #pragma unroll
            for (int j = 0; j < 2; ++j) {
                const int ks = 2 * ksp + j;
                const int kb = ks * 16 + 2 * (lane & 3);
                h[j * 4 + 0] = __float2half_rn(w[(size_t)(n * CIN + kb + 0) * KKn + kk]);
                h[j * 4 + 1] = __float2half_rn(w[(size_t)(n * CIN + kb + 1) * KKn + kk]);
                h[j * 4 + 2] = __float2half_rn(w[(size_t)(n * CIN + kb + 8) * KKn + kk]);
                h[j * 4 + 3] = __float2half_rn(w[(size_t)(n * CIN + kb + 9) * KKn + kk]);
            }
            g_wb[((kk * 8 + nt) * 2 + ksp) * 32 + lane] = *(const uint4*)h;
        }
    }
}

// ---------------------------------------------------------------------------
// Fused deformable conv, pipelined, 4m x 2n warp tiling.
// Block = one output row (b,y); warp = 32px x 32out. B fragments come straight
// from pre-permuted global (L1-resident), no W staging, no B ldsm.
// ---------------------------------------------------------------------------
__global__ void __launch_bounds__(256, 2) dcn_kernel(
    const float* __restrict__ offset,
    const float* __restrict__ bias,
    float* __restrict__ out)
{
    extern __shared__ char smem[];
    const uint32_t smb = smem_u32(smem);
    const int bid = blockIdx.x;
    const int b   = bid >> 7;
    const int y   = bid & 127;
    const int tid = threadIdx.x;
    const int wid = tid >> 5;
    const int lid = tid & 31;
    const int m0  = (wid & 3) * 32;      // warp px tile [m0, m0+32)
    const int n0  = (wid >> 2) * 32;     // warp out tile [n0, n0+32)

    float d[2][4][4];
    #pragma unroll
    for (int i = 0; i < 2; ++i)
        #pragma unroll
        for (int j = 0; j < 4; ++j)
            #pragma unroll
            for (int k = 0; k < 4; ++k)
                d[i][j][k] = 0.0f;

    const float* off_b = offset + (size_t)b * (2 * DGn * KKn * HWp) + (size_t)y * WOn;
    const __half* xh_b = g_xh + (size_t)b * (DGn * Hc * Wc * CGn);

    auto sample_tap = [&](int kk, uint32_t abase) {
        const int kh = kk / 3;
        const int kw = kk - kh * 3;
        #pragma unroll
        for (int it = 0; it < 4; ++it) {
            const int t  = tid + it * 256;
            const int dg = t >> 7;
            const int px = t & 127;

            const float* op = off_b + (size_t)((dg * KKn + kk) * 2) * HWp + px;
            const float oy = op[0];
            const float ox = op[HWp];

            const float py  = (float)(y - 1 + kh) + oy;
            const float pxx = (float)(px - 1 + kw) + ox;
            const float y0f = floorf(py);
            const float x0f = floorf(pxx);
            const float ly  = py - y0f;
            const float lx  = pxx - x0f;
            const int y0 = (int)y0f;
            const int x0 = (int)x0f;
            const float hy = 1.0f - ly, hx = 1.0f - lx;

            float w00 = hy * hx, w01 = hy * lx, w10 = ly * hx, w11 = ly * lx;
            const bool yv0 = (y0 >= 0) && (y0 < Hc);
            const bool yv1 = (y0 + 1 >= 0) && (y0 + 1 < Hc);
            const bool xv0 = (x0 >= 0) && (x0 < Wc);
            const bool xv1 = (x0 + 1 >= 0) && (x0 + 1 < Wc);
            if (!(yv0 && xv0)) w00 = 0.0f;
            if (!(yv0 && xv1)) w01 = 0.0f;
            if (!(yv1 && xv0)) w10 = 0.0f;
            if (!(yv1 && xv1)) w11 = 0.0f;

            const int iy0 = min(max(y0, 0), Hc - 1);
            const int iy1 = min(max(y0 + 1, 0), Hc - 1);
            const int ix0 = min(max(x0, 0), Wc - 1);
            const int ix1 = min(max(x0 + 1, 0), Wc - 1);

            const __half* xg = xh_b + (size_t)dg * (Hc * Wc * CGn);
            const uint4 q00 = *(const uint4*)(xg + (size_t)(iy0 * Wc + ix0) * CGn);
            const uint4 q01 = *(const uint4*)(xg + (size_t)(iy0 * Wc + ix1) * CGn);
            const uint4 q10 = *(const uint4*)(xg + (size_t)(iy1 * Wc + ix0) * CGn);
            const uint4 q11 = *(const uint4*)(xg + (size_t)(iy1 * Wc + ix1) * CGn);
            const __half2* c00 = (const __half2*)&q00;
            const __half2* c01 = (const __half2*)&q01;
            const __half2* c10 = (const __half2*)&q10;
            const __half2* c11 = (const __half2*)&q11;

            const __half2 wv00 = __float2half2_rn(w00);
            const __half2 wv01 = __float2half2_rn(w01);
            const __half2 wv10 = __float2half2_rn(w10);
            const __half2 wv11 = __float2half2_rn(w11);

            __half2 v2[4];
            #pragma unroll
            for (int j = 0; j < 4; ++j) {
                __half2 acc = __hmul2(c00[j], wv00);
                acc = __hfma2(c01[j], wv01, acc);
                acc = __hfma2(c10[j], wv10, acc);
                acc = __hfma2(c11[j], wv11, acc);
                v2[j] = acc;
            }
            const uint32_t aoff = SWZ((uint32_t)(px * 128 + dg * 16));
            *(uint4*)(smem + abase + aoff) = *(const uint4*)v2;
        }
    };

    // prologue
    sample_tap(0, SM_A0);
    __syncthreads();

    for (int kk = 0; kk < KKn; ++kk) {
        const uint32_t cur = (kk & 1) ? SM_A1 : SM_A0;
        const uint32_t nxt = (kk & 1) ? SM_A0 : SM_A1;

        if (kk + 1 < KKn) sample_tap(kk + 1, nxt);

        // ---- A fragments: 2 m16-frags x 4 k-steps ----
        uint32_t ah[2][4][4];
        #pragma unroll
        for (int mf = 0; mf < 2; ++mf) {
            const uint32_t arow = (uint32_t)(m0 + mf * 16 + (lid & 15));
            const uint32_t akg  = (uint32_t)(lid >> 4);
            #pragma unroll
            for (int ks = 0; ks < 4; ++ks) {
                const uint32_t off = SWZ(arow * 128 + (uint32_t)(ks * 32) + akg * 16);
                ldsm_x4(ah[mf][ks], smb + cur + off);
            }
        }

        // ---- B fragments straight from global; MMA ----
        const uint4* wbk = g_wb + (size_t)kk * (8 * 2 * 32);
        #pragma unroll
        for (int nt = 0; nt < 4; ++nt) {
            const int ntg = (n0 >> 3) + nt;
            #pragma unroll
            for (int ksp = 0; ksp < 2; ++ksp) {
                const uint4 bq = __ldg(&wbk[(ntg * 2 + ksp) * 32 + lid]);
                mma_f16(d[0][nt], ah[0][2 * ksp],     bq.x, bq.y);
                mma_f16(d[1][nt], ah[1][2 * ksp],     bq.x, bq.y);
                mma_f16(d[0][nt], ah[0][2 * ksp + 1], bq.z, bq.w);
                mma_f16(d[1][nt], ah[1][2 * ksp + 1], bq.z, bq.w);
            }
        }
        __syncthreads();
    }

    // ---- epilogue: fragments -> global, +bias ----
    {
        float* ob = out + (size_t)b * (COUT * HWp) + (size_t)y * WOn;
        #pragma unroll
        for (int mf = 0; mf < 2; ++mf) {
            const int px0 = m0 + mf * 16 + (lid >> 2);
            #pragma unroll
            for (int nt = 0; nt < 4; ++nt) {
                const int o0 = n0 + nt * 8 + 2 * (lid & 3);
                const float2 bv = *(const float2*)&bias[o0];
                ob[(size_t)o0 * HWp + px0]           = d[mf][nt][0] + bv.x;
                ob[(size_t)(o0 + 1) * HWp + px0]     = d[mf][nt][1] + bv.y;
                ob[(size_t)o0 * HWp + px0 + 8]       = d[mf][nt][2] + bv.x;
                ob[(size_t)(o0 + 1) * HWp + px0 + 8] = d[mf][nt][3] + bv.y;
            }
        }
    }
}

extern "C" void kernel_launch(void* const* d_in, const int* in_sizes, int n_in,
                              void* d_out, int out_size) {
    const float* x      = (const float*)d_in[0];
    const float* offset = (const float*)d_in[1];
    const float* weight = (const float*)d_in[2];
    const float* bias   = (const float*)d_in[3];
    float* out = (float*)d_out;

    cudaFuncSetAttribute(dcn_kernel, cudaFuncAttributeMaxDynamicSharedMemorySize, SM_TOTAL);

    prep_kernel<<<1024 + KKn, 256>>>(x, weight);
    dcn_kernel<<<Bn * HOn, 256, SM_TOTAL>>>(offset, bias, out);
}